// round 16
// baseline (speedup 1.0000x reference)
#include <cuda_runtime.h>
#include <math.h>

// x, x_r : (1, 3, 32, 512, 512) float32
// size=64 -> hc=wc=32 ; 16x16 patches per frame ; t=32
// patch mean = sum(|x-x_r|)/(2*3072) ; out = log(mean_t(max_patches))
// Deferred scaling: out = log( sum_t(max_p sum|dx|) / (32*6144) )
//
// DOUBLE-SLAB kernel: CTA = (t, ph-pair) = 64 full 512-wide rows x 3 ch ->
// six 128KB contiguous streams per CTA (2x R15's, which lifted DRAM to 78%).
// 256 CTAs x 1024 threads, occ 2 (single wave, 256<=296 slots). Both
// ph-patch-rows of the pair reduced in-CTA (two accumulators per thread);
// fence-free join protocol identical to R15.

#define T_DIM 32
#define NCTA 256             // 32 t * 8 ph-pairs
#define HW 512
#define TSTRIDE (512u * 512u)
#define CSTRIDE (32u * 512u * 512u)

__device__ int          g_frame_max[T_DIM];   // float bits; >=0 so int order == float order
__device__ unsigned int g_done_count;

__device__ __forceinline__ float4 ldcs4(const float* p) {
    float4 v;
    asm volatile("ld.global.cs.v4.f32 {%0,%1,%2,%3}, [%4];"
                 : "=f"(v.x), "=f"(v.y), "=f"(v.z), "=f"(v.w) : "l"(p));
    return v;
}

__global__ __launch_bounds__(1024, 2)
void patch_loss_kernel(const float* __restrict__ x, const float* __restrict__ xr,
                       float* __restrict__ out) {
    const int bid = blockIdx.x;
    const int t   = bid >> 3;
    const int phg = bid & 7;                  // ph pair: covers ph = 2*phg, 2*phg+1
    const int tid = threadIdx.x;
    const int wid = tid >> 5, lane = tid & 31;

    // 1024 threads x float4 = 4096 floats = 8 rows per step; 8 steps = 64 rows.
    // Thread's float column is fixed -> pw = colf/32 fixed.
    const int rowoff = tid >> 7;              // 0..7 row within each 8-row step
    const int colf   = (tid & 127) << 2;      // 0..508
    const size_t base = (size_t)t * TSTRIDE
                      + (size_t)(phg * 64 + rowoff) * HW
                      + (size_t)colf;
    const float* px = x  + base;
    const float* pr = xr + base;

    float acc0 = 0.0f, acc1 = 0.0f;           // rows [0,32) / [32,64) of the pair
    #pragma unroll
    for (int c = 0; c < 3; ++c) {
        #pragma unroll
        for (int i = 0; i < 8; ++i) {         // serial pairs (measured-best MLP)
            const size_t off = (size_t)c * CSTRIDE + (size_t)i * (8u * HW);
            const float4 a = ldcs4(px + off);
            const float4 b = ldcs4(pr + off);
            const float d = fabsf(a.x - b.x) + fabsf(a.y - b.y)
                          + fabsf(a.z - b.z) + fabsf(a.w - b.w);
            if (i < 4) acc0 += d; else acc1 += d;
        }
    }

    // 8-lane segmented reduce (lanes sharing one pw)
    #pragma unroll
    for (int o = 4; o > 0; o >>= 1) {
        acc0 += __shfl_xor_sync(0xFFFFFFFFu, acc0, o);
        acc1 += __shfl_xor_sync(0xFFFFFFFFu, acc1, o);
    }

    // warp w: pw = (w&3)*4 + lane/8 ; row-group = w>>2 (0..7)
    __shared__ float s[2][16][8];
    if ((lane & 7) == 0) {
        const int pw = ((wid & 3) << 2) + (lane >> 3);
        s[0][pw][wid >> 2] = acc0;
        s[1][pw][wid >> 2] = acc1;
    }
    __syncthreads();

    if (tid < 32) {
        unsigned int prev = 0;
        {   // thread j owns patch (t, ph = 2*phg + j/16, pw = j%16)
            const int sub = tid >> 4, pw = tid & 15;
            float total = 0.0f;
            #pragma unroll
            for (int g = 0; g < 8; ++g) total += s[sub][pw][g];
            asm volatile("red.global.max.s32 [%0], %1;"
                         :: "l"(&g_frame_max[t]), "r"(__float_as_int(total)) : "memory");
        }
        __syncwarp();
        if (tid == 0) {
            asm volatile("atom.release.gpu.global.add.u32 %0, [%1], 1;"
                         : "=r"(prev) : "l"(&g_done_count) : "memory");
        }
        prev = __shfl_sync(0xFFFFFFFFu, prev, 0);

        if (prev == NCTA - 1) {               // last CTA: finalize
            asm volatile("fence.acq_rel.gpu;" ::: "memory");
            float sum = __int_as_float(__ldcg(&g_frame_max[tid]));
            #pragma unroll
            for (int o = 16; o > 0; o >>= 1)
                sum += __shfl_xor_sync(0xFFFFFFFFu, sum, o);
            if (tid == 0) {
                *out = logf(sum / (32.0f * 6144.0f));
                g_done_count = 0u;            // re-arm for next replay
            }
            __syncwarp();
            g_frame_max[tid] = 0;             // re-arm (after reads)
        }
    }
}

extern "C" void kernel_launch(void* const* d_in, const int* in_sizes, int n_in,
                              void* d_out, int out_size) {
    const float* x  = (const float*)d_in[0];
    const float* xr = (const float*)d_in[1];
    patch_loss_kernel<<<NCTA, 1024>>>(x, xr, (float*)d_out);
}